// round 10
// baseline (speedup 1.0000x reference)
#include <cuda_runtime.h>

#define NN 50000
#define NE 800000
#define DD 128

// Scratch (no runtime allocation allowed)
__device__ float g_h[NN * DD];       // h' = dinv[i] * (transformed features)
__device__ float g_agg[NN * DD];     // pre-scaled aggregation: agg' = agg / dinv
__device__ float g_dinv[NN];
__device__ int   g_deg[NN];          // degree incl. self-loop
__device__ int   g_off[NN + 1];      // CSR offsets (edge-only, exclusive scan)
__device__ int   g_cur[NN];          // fill cursors
__device__ int2  g_edge[NE];         // packed (src, dst) int32
__device__ int   g_srclist[NE];      // CSR: src ids grouped by dst
__device__ int   g_is64;             // edge_index dtype flag

// ---------------- init ----------------

__global__ void deg_init_kernel() {
    int i = blockIdx.x * blockDim.x + threadIdx.x;
    if (i < NN) { g_deg[i] = 1; g_cur[i] = 0; }  // self-loop contributes 1
}

// Detect edge_index dtype. int64 layout (values < 2^31, nonneg): every odd
// int32 word of the first 64 elements is 0. int32 layout: those words are
// random node ids — all-zero probability ~(1/50000)^64, negligible.
__global__ void detect_kernel(const int* __restrict__ ew) {
    if (threadIdx.x == 0 && blockIdx.x == 0) {
        int all0 = 1;
        for (int j = 0; j < 64; j++)
            if (ew[2 * j + 1] != 0) { all0 = 0; break; }
        g_is64 = all0;
    }
}

// Pack edges to int2 (bounds-guarded) and count in-degrees in one pass.
__global__ void pack_count_kernel(const void* __restrict__ edges, int E) {
    int e = blockIdx.x * blockDim.x + threadIdx.x;
    if (e >= E) return;
    int s, d;
    if (g_is64) {
        const long long* p = (const long long*)edges;
        s = (int)p[e];
        d = (int)p[(size_t)E + e];
    } else {
        const int* p = (const int*)edges;
        s = p[e];
        d = p[(size_t)E + e];
    }
    if ((unsigned)s >= NN) s = 0;  // defensive: never trap on bad data
    if ((unsigned)d >= NN) d = 0;
    g_edge[e] = make_int2(s, d);
    atomicAdd(&g_deg[d], 1);
}

__global__ void dinv_kernel() {
    int i = blockIdx.x * blockDim.x + threadIdx.x;
    if (i < NN) g_dinv[i] = rsqrtf((float)g_deg[i]);  // deg >= 1 always
}

// Blocked exclusive scan of (deg-1) into g_off. One block, 1024 threads:
// thread-local chunk sums -> one 1024-wide shared scan -> serial write-back.
__global__ void scan_kernel() {
    __shared__ int ssum[1024];
    const int C = (NN + 1023) / 1024;  // 49
    int t = threadIdx.x;
    int lo = t * C;
    int hi = lo + C; if (hi > NN) hi = NN;
    int local = 0;
    for (int i = lo; i < hi; i++) local += g_deg[i] - 1;
    ssum[t] = local;
    __syncthreads();
    for (int o = 1; o < 1024; o <<= 1) {
        int v = (t >= o) ? ssum[t - o] : 0;
        __syncthreads();
        ssum[t] += v;
        __syncthreads();
    }
    int run = ssum[t] - local;  // exclusive prefix of this chunk
    for (int i = lo; i < hi; i++) {
        g_off[i] = run;
        run += g_deg[i] - 1;
    }
    if (t == 1023) g_off[NN] = run;
}

// Fill CSR src lists (int cursor atomics only)
__global__ void fill_kernel(int E) {
    int e = blockIdx.x * blockDim.x + threadIdx.x;
    if (e >= E) return;
    int2 sd = g_edge[e];
    int pos = atomicAdd(&g_cur[sd.y], 1);
    g_srclist[g_off[sd.y] + pos] = sd.x;
}

// ---- GEMM: g_h = dinv * (act(X') @ W), X' = optionally dinv*X (+bias, relu) ----
// Norm factorization: agg[d] = dinv[d] * (h'[d] + sum_in-edges h'[src]).
// in_src: 0 -> read from X arg; 1 -> read from g_agg (layer 2).
// Block: 256 threads, 64 rows. W staged in smem (64KB) + X tile (32KB).
// Safe when reading g_agg: each block stages its 64 rows into smem before any
// write; epilogue writes only g_h.
__global__ __launch_bounds__(256, 2) void gemm_kernel(
    const float* __restrict__ X, const float* __restrict__ W,
    const float* __restrict__ bin, int relu_in, int in_src, int M)
{
    extern __shared__ float smem[];
    float* sW = smem;            // 128*128
    float* sX = smem + DD * DD;  // 64*128

    int tid = threadIdx.x;
    int row0 = blockIdx.x * 64;
    const float* Xp = in_src ? g_agg : X;

    const float4* W4 = (const float4*)W;
    float4* sW4 = (float4*)sW;
    for (int idx = tid; idx < DD * DD / 4; idx += 256) sW4[idx] = W4[idx];

    float4* sX4 = (float4*)sX;
    for (int idx = tid; idx < 64 * DD / 4; idx += 256) {
        int r = idx >> 5;
        int c4 = idx & 31;
        int row = row0 + r;
        float4 v = make_float4(0.f, 0.f, 0.f, 0.f);
        if (row < M) {
            v = ((const float4*)(Xp + (size_t)row * DD))[c4];
            if (in_src) {  // deferred dinv scale of agg'
                float dv = g_dinv[row];
                v.x *= dv; v.y *= dv; v.z *= dv; v.w *= dv;
            }
        }
        if (relu_in) {
            float4 b = ((const float4*)bin)[c4];
            v.x = fmaxf(v.x + b.x, 0.f);
            v.y = fmaxf(v.y + b.y, 0.f);
            v.z = fmaxf(v.z + b.z, 0.f);
            v.w = fmaxf(v.w + b.w, 0.f);
        }
        sX4[idx] = v;
    }
    __syncthreads();

    int lane = tid & 31, wid = tid >> 5;
    float4 acc[8];
#pragma unroll
    for (int r = 0; r < 8; r++) acc[r] = make_float4(0.f, 0.f, 0.f, 0.f);

    const float* xbase = sX + (wid * 8) * DD;
#pragma unroll 4
    for (int k = 0; k < DD; k++) {
        float4 w = ((const float4*)(sW + k * DD))[lane];
#pragma unroll
        for (int r = 0; r < 8; r++) {
            float xv = xbase[r * DD + k];
            acc[r].x = fmaf(xv, w.x, acc[r].x);
            acc[r].y = fmaf(xv, w.y, acc[r].y);
            acc[r].z = fmaf(xv, w.z, acc[r].z);
            acc[r].w = fmaf(xv, w.w, acc[r].w);
        }
    }

#pragma unroll
    for (int r = 0; r < 8; r++) {
        int row = row0 + wid * 8 + r;
        if (row < M) {
            float dv = g_dinv[row];
            float4 a = acc[r];
            a.x *= dv; a.y *= dv; a.z *= dv; a.w *= dv;   // h' = dinv * h
            ((float4*)(g_h + (size_t)row * DD))[lane] = a;
        }
    }
}

// ---------------- gather-side aggregation (CSR, no float atomics) ----------------
// Warp per node: acc = h'[i] (self-loop) + sum over in-edges h'[src].
// mode 0: store agg' (layer 1). mode 1: fused readout (layer 2):
// out[i] = sigmoid((dinv*acc + b2)@Wl + bl), entirely in registers.
__global__ void gather_agg_kernel(int mode,
                                  const float* __restrict__ b2,
                                  const float* __restrict__ Wl,
                                  const float* __restrict__ bl,
                                  float* __restrict__ out, int M) {
    int i = (int)((blockIdx.x * (unsigned)blockDim.x + threadIdx.x) >> 5);
    if (i >= M) return;
    int lane = threadIdx.x & 31;

    float4 acc = ((const float4*)(g_h + (size_t)i * DD))[lane];  // self-loop
    int beg = g_off[i];
    int end = g_off[i + 1];

    int e = beg;
    for (; e + 3 < end; e += 4) {
        int s0 = g_srclist[e];
        int s1 = g_srclist[e + 1];
        int s2 = g_srclist[e + 2];
        int s3 = g_srclist[e + 3];
        float4 v0 = ((const float4*)(g_h + (size_t)s0 * DD))[lane];
        float4 v1 = ((const float4*)(g_h + (size_t)s1 * DD))[lane];
        float4 v2 = ((const float4*)(g_h + (size_t)s2 * DD))[lane];
        float4 v3 = ((const float4*)(g_h + (size_t)s3 * DD))[lane];
        acc.x += (v0.x + v1.x) + (v2.x + v3.x);
        acc.y += (v0.y + v1.y) + (v2.y + v3.y);
        acc.z += (v0.z + v1.z) + (v2.z + v3.z);
        acc.w += (v0.w + v1.w) + (v2.w + v3.w);
    }
    for (; e < end; e++) {
        int s = g_srclist[e];
        float4 v = ((const float4*)(g_h + (size_t)s * DD))[lane];
        acc.x += v.x; acc.y += v.y; acc.z += v.z; acc.w += v.w;
    }

    if (mode == 0) {
        ((float4*)(g_agg + (size_t)i * DD))[lane] = acc;
    } else {
        float dv = g_dinv[i];
        float4 b = ((const float4*)b2)[lane];
        float4 w = ((const float4*)Wl)[lane];
        float p = fmaf(dv, acc.x, b.x) * w.x + fmaf(dv, acc.y, b.y) * w.y +
                  fmaf(dv, acc.z, b.z) * w.z + fmaf(dv, acc.w, b.w) * w.w;
#pragma unroll
        for (int o = 16; o; o >>= 1) p += __shfl_down_sync(0xffffffffu, p, o);
        if (lane == 0) out[i] = 1.f / (1.f + expf(-(p + bl[0])));
    }
}

// ---------------- launch ----------------

extern "C" void kernel_launch(void* const* d_in, const int* in_sizes, int n_in,
                              void* d_out, int out_size) {
    const float* x  = (const float*)d_in[0];
    const void*  ei = d_in[1];                // int32 or int64 — detected on device
    const float* W1 = (const float*)d_in[2];
    const float* b1 = (const float*)d_in[3];
    const float* W2 = (const float*)d_in[4];
    const float* b2 = (const float*)d_in[5];
    const float* Wl = (const float*)d_in[6];
    const float* bl = (const float*)d_in[7];
    float* out = (float*)d_out;

    int E = in_sizes[1] / 2;      // element count / 2 = edges (either dtype)
    int M = in_sizes[0] / DD;

    const int GEMM_SMEM = (DD * DD + 64 * DD) * (int)sizeof(float);  // 96KB
    cudaFuncSetAttribute(gemm_kernel, cudaFuncAttributeMaxDynamicSharedMemorySize, GEMM_SMEM);

    int nb_nodes  = (NN + 255) / 256;
    int nb_edges  = (E + 255) / 256;
    int nb_gemm   = (M + 63) / 64;
    int nb_rows32 = (M * 32 + 255) / 256;

    // ---- prep: dtype detect, degrees, dinv, CSR ----
    deg_init_kernel<<<nb_nodes, 256>>>();
    detect_kernel<<<1, 32>>>((const int*)ei);
    pack_count_kernel<<<nb_edges, 256>>>(ei, E);
    dinv_kernel<<<nb_nodes, 256>>>();
    scan_kernel<<<1, 1024>>>();
    fill_kernel<<<nb_edges, 256>>>(E);

    // layer 1: h' = dinv * (x @ W1) ; agg' = gather(h')
    gemm_kernel<<<nb_gemm, 256, GEMM_SMEM>>>(x, W1, nullptr, 0, 0, M);
    gather_agg_kernel<<<nb_rows32, 256>>>(0, nullptr, nullptr, nullptr, nullptr, M);

    // layer 2: h' = dinv * (relu(dinv*agg' + b1) @ W2) ; fused gather + readout
    gemm_kernel<<<nb_gemm, 256, GEMM_SMEM>>>(nullptr, W2, b1, 1, 1, M);
    gather_agg_kernel<<<nb_rows32, 256>>>(1, b2, Wl, bl, out, M);
}

// round 12
// speedup vs baseline: 1.2003x; 1.2003x over previous
#include <cuda_runtime.h>

#define NN 50000
#define NE 800000
#define DD 128

// Scratch (no runtime allocation allowed)
__device__ float g_h[NN * DD];       // h' = dinv[i] * (transformed features)
__device__ float g_agg[NN * DD];     // pre-scaled aggregation: agg' = agg / dinv
__device__ float g_dinv[NN];
__device__ int   g_deg[NN];          // degree incl. self-loop
__device__ int   g_off[NN];          // CSR region start per node (bump-allocated)
__device__ int   g_cur[NN];          // fill cursors
__device__ int2  g_edge[NE];         // packed (src, dst) int32
__device__ int   g_srclist[NE];      // CSR: src ids grouped by dst
__device__ int   g_is64;             // edge_index dtype flag
__device__ int   g_total;            // bump allocator for CSR regions

// ---------------- init ----------------

__global__ void deg_init_kernel() {
    int i = blockIdx.x * blockDim.x + threadIdx.x;
    if (i < NN) { g_deg[i] = 1; g_cur[i] = 0; }  // self-loop contributes 1
    if (i == 0) g_total = 0;
}

// Detect edge_index dtype. int64 layout (values < 2^31, nonneg): every odd
// int32 word of the first 64 elements is 0. int32 layout: those words are
// random node ids — all-zero probability ~(1/50000)^64, negligible.
__global__ void detect_kernel(const int* __restrict__ ew) {
    __shared__ int bad;
    if (threadIdx.x == 0) bad = 0;
    __syncthreads();
    if (threadIdx.x < 64 && ew[2 * threadIdx.x + 1] != 0) atomicAdd(&bad, 1);
    __syncthreads();
    if (threadIdx.x == 0) g_is64 = (bad == 0);
}

// Pack edges to int2 (bounds-guarded) and count in-degrees in one pass.
__global__ void pack_count_kernel(const void* __restrict__ edges, int E) {
    int e = blockIdx.x * blockDim.x + threadIdx.x;
    if (e >= E) return;
    int s, d;
    if (g_is64) {
        const long long* p = (const long long*)edges;
        s = (int)p[e];
        d = (int)p[(size_t)E + e];
    } else {
        const int* p = (const int*)edges;
        s = p[e];
        d = p[(size_t)E + e];
    }
    if ((unsigned)s >= NN) s = 0;  // defensive: never trap on bad data
    if ((unsigned)d >= NN) d = 0;
    g_edge[e] = make_int2(s, d);
    atomicAdd(&g_deg[d], 1);
}

// dinv + CSR region allocation. CSR regions need only be DISJOINT, not ordered
// by node id — so instead of a global scan, each warp prefix-sums its 32
// (deg-1) values via shfl and bump-allocates one contiguous chunk with a
// single atomicAdd (1563 atomics total). Region of node i: [g_off[i],
// g_off[i] + deg[i]-1).
__global__ void dinv_off_kernel() {
    int i = blockIdx.x * blockDim.x + threadIdx.x;
    int lane = threadIdx.x & 31;
    int v = 0;
    if (i < NN) {
        int deg = g_deg[i];
        g_dinv[i] = rsqrtf((float)deg);  // deg >= 1 always
        v = deg - 1;
    }
    int sum = v;  // warp inclusive scan
#pragma unroll
    for (int o = 1; o < 32; o <<= 1) {
        int t = __shfl_up_sync(0xffffffffu, sum, o);
        if (lane >= o) sum += t;
    }
    int base = 0;
    if (lane == 31) base = atomicAdd(&g_total, sum);
    base = __shfl_sync(0xffffffffu, base, 31);
    if (i < NN) g_off[i] = base + sum - v;  // exclusive within warp chunk
}

// Fill CSR src lists (int cursor atomics only; intra-list order arbitrary —
// fp-add reordering, same tolerance class as any atomic scheme)
__global__ void fill_kernel(int E) {
    int e = blockIdx.x * blockDim.x + threadIdx.x;
    if (e >= E) return;
    int2 sd = g_edge[e];
    int pos = atomicAdd(&g_cur[sd.y], 1);
    g_srclist[g_off[sd.y] + pos] = sd.x;
}

// ---- GEMM: g_h = dinv * (act(X') @ W), X' = optionally dinv*X (+bias, relu) ----
// Norm factorization: agg[d] = dinv[d] * (h'[d] + sum_in-edges h'[src]).
// in_src: 0 -> read from X arg; 1 -> read from g_agg (layer 2).
// Block: 256 threads, 64 rows. W staged in smem (64KB) + X tile (32KB).
// Safe when reading g_agg: each block stages its 64 rows into smem before any
// write; epilogue writes only g_h.
__global__ __launch_bounds__(256, 2) void gemm_kernel(
    const float* __restrict__ X, const float* __restrict__ W,
    const float* __restrict__ bin, int relu_in, int in_src, int M)
{
    extern __shared__ float smem[];
    float* sW = smem;            // 128*128
    float* sX = smem + DD * DD;  // 64*128

    int tid = threadIdx.x;
    int row0 = blockIdx.x * 64;
    const float* Xp = in_src ? g_agg : X;

    const float4* W4 = (const float4*)W;
    float4* sW4 = (float4*)sW;
    for (int idx = tid; idx < DD * DD / 4; idx += 256) sW4[idx] = W4[idx];

    float4* sX4 = (float4*)sX;
    for (int idx = tid; idx < 64 * DD / 4; idx += 256) {
        int r = idx >> 5;
        int c4 = idx & 31;
        int row = row0 + r;
        float4 v = make_float4(0.f, 0.f, 0.f, 0.f);
        if (row < M) {
            v = ((const float4*)(Xp + (size_t)row * DD))[c4];
            if (in_src) {  // deferred dinv scale of agg'
                float dv = g_dinv[row];
                v.x *= dv; v.y *= dv; v.z *= dv; v.w *= dv;
            }
        }
        if (relu_in) {
            float4 b = ((const float4*)bin)[c4];
            v.x = fmaxf(v.x + b.x, 0.f);
            v.y = fmaxf(v.y + b.y, 0.f);
            v.z = fmaxf(v.z + b.z, 0.f);
            v.w = fmaxf(v.w + b.w, 0.f);
        }
        sX4[idx] = v;
    }
    __syncthreads();

    int lane = tid & 31, wid = tid >> 5;
    float4 acc[8];
#pragma unroll
    for (int r = 0; r < 8; r++) acc[r] = make_float4(0.f, 0.f, 0.f, 0.f);

    const float* xbase = sX + (wid * 8) * DD;
#pragma unroll 4
    for (int k = 0; k < DD; k++) {
        float4 w = ((const float4*)(sW + k * DD))[lane];
#pragma unroll
        for (int r = 0; r < 8; r++) {
            float xv = xbase[r * DD + k];
            acc[r].x = fmaf(xv, w.x, acc[r].x);
            acc[r].y = fmaf(xv, w.y, acc[r].y);
            acc[r].z = fmaf(xv, w.z, acc[r].z);
            acc[r].w = fmaf(xv, w.w, acc[r].w);
        }
    }

#pragma unroll
    for (int r = 0; r < 8; r++) {
        int row = row0 + wid * 8 + r;
        if (row < M) {
            float dv = g_dinv[row];
            float4 a = acc[r];
            a.x *= dv; a.y *= dv; a.z *= dv; a.w *= dv;   // h' = dinv * h
            ((float4*)(g_h + (size_t)row * DD))[lane] = a;
        }
    }
}

// ---------------- gather-side aggregation (CSR, no float atomics) ----------------
// Warp per node: acc = h'[i] (self-loop) + sum over in-edges h'[src].
// Region: [g_off[i], g_off[i] + g_deg[i]-1). 8-way unroll -> MLP=8 on the
// 512B coalesced gathers (mean degree ~16 -> ~2 batches/node).
// mode 0: store agg' (layer 1). mode 1: fused readout (layer 2):
// out[i] = sigmoid((dinv*acc + b2)@Wl + bl), entirely in registers.
__global__ void gather_agg_kernel(int mode,
                                  const float* __restrict__ b2,
                                  const float* __restrict__ Wl,
                                  const float* __restrict__ bl,
                                  float* __restrict__ out, int M) {
    int i = (int)((blockIdx.x * (unsigned)blockDim.x + threadIdx.x) >> 5);
    if (i >= M) return;
    int lane = threadIdx.x & 31;

    float4 acc = ((const float4*)(g_h + (size_t)i * DD))[lane];  // self-loop
    int beg = g_off[i];
    int end = beg + g_deg[i] - 1;

    int e = beg;
    for (; e + 7 < end; e += 8) {
        int s0 = g_srclist[e];
        int s1 = g_srclist[e + 1];
        int s2 = g_srclist[e + 2];
        int s3 = g_srclist[e + 3];
        int s4 = g_srclist[e + 4];
        int s5 = g_srclist[e + 5];
        int s6 = g_srclist[e + 6];
        int s7 = g_srclist[e + 7];
        float4 v0 = ((const float4*)(g_h + (size_t)s0 * DD))[lane];
        float4 v1 = ((const float4*)(g_h + (size_t)s1 * DD))[lane];
        float4 v2 = ((const float4*)(g_h + (size_t)s2 * DD))[lane];
        float4 v3 = ((const float4*)(g_h + (size_t)s3 * DD))[lane];
        float4 v4 = ((const float4*)(g_h + (size_t)s4 * DD))[lane];
        float4 v5 = ((const float4*)(g_h + (size_t)s5 * DD))[lane];
        float4 v6 = ((const float4*)(g_h + (size_t)s6 * DD))[lane];
        float4 v7 = ((const float4*)(g_h + (size_t)s7 * DD))[lane];
        acc.x += ((v0.x + v1.x) + (v2.x + v3.x)) + ((v4.x + v5.x) + (v6.x + v7.x));
        acc.y += ((v0.y + v1.y) + (v2.y + v3.y)) + ((v4.y + v5.y) + (v6.y + v7.y));
        acc.z += ((v0.z + v1.z) + (v2.z + v3.z)) + ((v4.z + v5.z) + (v6.z + v7.z));
        acc.w += ((v0.w + v1.w) + (v2.w + v3.w)) + ((v4.w + v5.w) + (v6.w + v7.w));
    }
    for (; e + 3 < end; e += 4) {
        int s0 = g_srclist[e];
        int s1 = g_srclist[e + 1];
        int s2 = g_srclist[e + 2];
        int s3 = g_srclist[e + 3];
        float4 v0 = ((const float4*)(g_h + (size_t)s0 * DD))[lane];
        float4 v1 = ((const float4*)(g_h + (size_t)s1 * DD))[lane];
        float4 v2 = ((const float4*)(g_h + (size_t)s2 * DD))[lane];
        float4 v3 = ((const float4*)(g_h + (size_t)s3 * DD))[lane];
        acc.x += (v0.x + v1.x) + (v2.x + v3.x);
        acc.y += (v0.y + v1.y) + (v2.y + v3.y);
        acc.z += (v0.z + v1.z) + (v2.z + v3.z);
        acc.w += (v0.w + v1.w) + (v2.w + v3.w);
    }
    for (; e < end; e++) {
        int s = g_srclist[e];
        float4 v = ((const float4*)(g_h + (size_t)s * DD))[lane];
        acc.x += v.x; acc.y += v.y; acc.z += v.z; acc.w += v.w;
    }

    if (mode == 0) {
        ((float4*)(g_agg + (size_t)i * DD))[lane] = acc;
    } else {
        float dv = g_dinv[i];
        float4 b = ((const float4*)b2)[lane];
        float4 w = ((const float4*)Wl)[lane];
        float p = fmaf(dv, acc.x, b.x) * w.x + fmaf(dv, acc.y, b.y) * w.y +
                  fmaf(dv, acc.z, b.z) * w.z + fmaf(dv, acc.w, b.w) * w.w;
#pragma unroll
        for (int o = 16; o; o >>= 1) p += __shfl_down_sync(0xffffffffu, p, o);
        if (lane == 0) out[i] = 1.f / (1.f + expf(-(p + bl[0])));
    }
}

// ---------------- launch ----------------

extern "C" void kernel_launch(void* const* d_in, const int* in_sizes, int n_in,
                              void* d_out, int out_size) {
    const float* x  = (const float*)d_in[0];
    const void*  ei = d_in[1];                // int32 or int64 — detected on device
    const float* W1 = (const float*)d_in[2];
    const float* b1 = (const float*)d_in[3];
    const float* W2 = (const float*)d_in[4];
    const float* b2 = (const float*)d_in[5];
    const float* Wl = (const float*)d_in[6];
    const float* bl = (const float*)d_in[7];
    float* out = (float*)d_out;

    int E = in_sizes[1] / 2;      // element count / 2 = edges (either dtype)
    int M = in_sizes[0] / DD;

    const int GEMM_SMEM = (DD * DD + 64 * DD) * (int)sizeof(float);  // 96KB
    cudaFuncSetAttribute(gemm_kernel, cudaFuncAttributeMaxDynamicSharedMemorySize, GEMM_SMEM);

    int nb_nodes  = (NN + 255) / 256;
    int nb_edges  = (E + 255) / 256;
    int nb_gemm   = (M + 63) / 64;
    int nb_rows32 = (M * 32 + 255) / 256;

    // ---- prep: dtype detect, degrees, dinv + CSR offsets (no scan), fill ----
    deg_init_kernel<<<nb_nodes, 256>>>();
    detect_kernel<<<1, 64>>>((const int*)ei);
    pack_count_kernel<<<nb_edges, 256>>>(ei, E);
    dinv_off_kernel<<<nb_nodes, 256>>>();
    fill_kernel<<<nb_edges, 256>>>(E);

    // layer 1: h' = dinv * (x @ W1) ; agg' = gather(h')
    gemm_kernel<<<nb_gemm, 256, GEMM_SMEM>>>(x, W1, nullptr, 0, 0, M);
    gather_agg_kernel<<<nb_rows32, 256>>>(0, nullptr, nullptr, nullptr, nullptr, M);

    // layer 2: h' = dinv * (relu(dinv*agg' + b1) @ W2) ; fused gather + readout
    gemm_kernel<<<nb_gemm, 256, GEMM_SMEM>>>(nullptr, W2, b1, 1, 1, M);
    gather_agg_kernel<<<nb_rows32, 256>>>(1, b2, Wl, bl, out, M);
}

// round 13
// speedup vs baseline: 1.3029x; 1.0855x over previous
#include <cuda_runtime.h>

#define NN 50000
#define NE 800000
#define DD 128

// Scratch (no runtime allocation allowed)
__device__ float g_h[NN * DD];       // h' = dinv[i] * (transformed features)
__device__ float g_agg[NN * DD];     // pre-scaled aggregation: agg' = agg / dinv
__device__ float g_dinv[NN];
__device__ int   g_deg[NN];          // degree incl. self-loop
__device__ int   g_off[NN];          // CSR region start per node (bump-allocated)
__device__ int   g_cur[NN];          // fill cursors
__device__ int2  g_edge[NE];         // packed (src, dst) int32
__device__ int   g_srclist[NE];      // CSR: src ids grouped by dst
__device__ int   g_is64;             // edge_index dtype flag
__device__ int   g_total;            // bump allocator for CSR regions

// f32x2 packed-FMA helpers (FFMA2 — only reachable via PTX, 2x fp32 FMA/issue)
#define FFMA2(d, a, b) \
    asm("fma.rn.f32x2 %0, %1, %2, %0;" : "+l"(d) : "l"(a), "l"(b))
__device__ __forceinline__ unsigned long long pack2(float a, float b) {
    unsigned long long r;
    asm("mov.b64 %0, {%1, %2};" : "=l"(r) : "f"(a), "f"(b));
    return r;
}
__device__ __forceinline__ float pairsum(unsigned long long p) {
    float lo, hi;
    asm("mov.b64 {%0, %1}, %2;" : "=f"(lo), "=f"(hi) : "l"(p));
    return lo + hi;
}

// ---------------- init ----------------

__global__ void deg_init_kernel() {
    int i = blockIdx.x * blockDim.x + threadIdx.x;
    if (i < NN) { g_deg[i] = 1; g_cur[i] = 0; }  // self-loop contributes 1
    if (i == 0) g_total = 0;
}

// Detect edge_index dtype. int64 layout (values < 2^31, nonneg): every odd
// int32 word of the first 64 elements is 0. int32 layout: those words are
// random node ids — all-zero probability ~(1/50000)^64, negligible.
__global__ void detect_kernel(const int* __restrict__ ew) {
    __shared__ int bad;
    if (threadIdx.x == 0) bad = 0;
    __syncthreads();
    if (threadIdx.x < 64 && ew[2 * threadIdx.x + 1] != 0) atomicAdd(&bad, 1);
    __syncthreads();
    if (threadIdx.x == 0) g_is64 = (bad == 0);
}

// Pack edges to int2 (bounds-guarded) and count in-degrees in one pass.
__global__ void pack_count_kernel(const void* __restrict__ edges, int E) {
    int e = blockIdx.x * blockDim.x + threadIdx.x;
    if (e >= E) return;
    int s, d;
    if (g_is64) {
        const long long* p = (const long long*)edges;
        s = (int)p[e];
        d = (int)p[(size_t)E + e];
    } else {
        const int* p = (const int*)edges;
        s = p[e];
        d = p[(size_t)E + e];
    }
    if ((unsigned)s >= NN) s = 0;  // defensive: never trap on bad data
    if ((unsigned)d >= NN) d = 0;
    g_edge[e] = make_int2(s, d);
    atomicAdd(&g_deg[d], 1);
}

// dinv + CSR region allocation: warp shfl-scan of (deg-1) + one bump atomic
// per warp. Region of node i: [g_off[i], g_off[i] + deg[i]-1). Regions are
// disjoint; ordering by node id is unnecessary.
__global__ void dinv_off_kernel() {
    int i = blockIdx.x * blockDim.x + threadIdx.x;
    int lane = threadIdx.x & 31;
    int v = 0;
    if (i < NN) {
        int deg = g_deg[i];
        g_dinv[i] = rsqrtf((float)deg);  // deg >= 1 always
        v = deg - 1;
    }
    int sum = v;  // warp inclusive scan
#pragma unroll
    for (int o = 1; o < 32; o <<= 1) {
        int t = __shfl_up_sync(0xffffffffu, sum, o);
        if (lane >= o) sum += t;
    }
    int base = 0;
    if (lane == 31) base = atomicAdd(&g_total, sum);
    base = __shfl_sync(0xffffffffu, base, 31);
    if (i < NN) g_off[i] = base + sum - v;  // exclusive within warp chunk
}

// Fill CSR src lists (int cursor atomics only; intra-list order arbitrary —
// fp-add reordering, same tolerance class as any atomic scheme)
__global__ void fill_kernel(int E) {
    int e = blockIdx.x * blockDim.x + threadIdx.x;
    if (e >= E) return;
    int2 sd = g_edge[e];
    int pos = atomicAdd(&g_cur[sd.y], 1);
    g_srclist[g_off[sd.y] + pos] = sd.x;
}

// ---- GEMM (FFMA2): g_h = dinv * (act(X') @ W) ----
// K dimension processed in pairs: accumulator holds (even-k, odd-k) partial
// sums in a packed f32x2; combined lo+hi at epilogue. Bit-class-identical
// fp32 math. W staged pair-interleaved: sWp[m*DD + j] = (W[2m][j], W[2m+1][j]).
// x pairs (x[r][2m], x[r][2m+1]) are contiguous -> LDS.64 broadcast.
// Per k-pair per warp: 2 LDS.128 (w) + 8 LDS.64 (x) + 32 FFMA2.
// Block: 256 threads, 64 rows; warp w rows [8w,8w+8), lane l cols [4l,4l+4).
// smem: 64KB packed W + 32KB X tile = 96KB -> 2 CTA/SM.
__global__ __launch_bounds__(256, 2) void gemm_kernel(
    const float* __restrict__ X, const float* __restrict__ W,
    const float* __restrict__ bin, int relu_in, int in_src, int M)
{
    extern __shared__ float smem[];
    unsigned long long* sWp = (unsigned long long*)smem;   // 64 pairs x 128 cols
    float* sX = smem + 2 * 64 * DD;                        // +16384 floats (64KB)

    int tid = threadIdx.x;
    int row0 = blockIdx.x * 64;
    const float* Xp = in_src ? g_agg : X;

    // Stage W pair-interleaved: idx -> (m, c4): read rows 2m, 2m+1 at cols
    // [4c4,4c4+4), write 4 packed pairs.
    for (int idx = tid; idx < 64 * 32; idx += 256) {
        int m = idx >> 5;
        int c4 = idx & 31;
        float4 r0 = ((const float4*)(W + (size_t)(2 * m) * DD))[c4];
        float4 r1 = ((const float4*)(W + (size_t)(2 * m + 1) * DD))[c4];
        unsigned long long* dst = sWp + m * DD + c4 * 4;
        dst[0] = pack2(r0.x, r1.x);
        dst[1] = pack2(r0.y, r1.y);
        dst[2] = pack2(r0.z, r1.z);
        dst[3] = pack2(r0.w, r1.w);
    }

    // Stage X tile (optionally deferred-dinv scale, then bias+relu)
    float4* sX4 = (float4*)sX;
    for (int idx = tid; idx < 64 * DD / 4; idx += 256) {
        int r = idx >> 5;
        int c4 = idx & 31;
        int row = row0 + r;
        float4 v = make_float4(0.f, 0.f, 0.f, 0.f);
        if (row < M) {
            v = ((const float4*)(Xp + (size_t)row * DD))[c4];
            if (in_src) {  // deferred dinv scale of agg'
                float dv = g_dinv[row];
                v.x *= dv; v.y *= dv; v.z *= dv; v.w *= dv;
            }
        }
        if (relu_in) {
            float4 b = ((const float4*)bin)[c4];
            v.x = fmaxf(v.x + b.x, 0.f);
            v.y = fmaxf(v.y + b.y, 0.f);
            v.z = fmaxf(v.z + b.z, 0.f);
            v.w = fmaxf(v.w + b.w, 0.f);
        }
        sX4[idx] = v;
    }
    __syncthreads();

    int lane = tid & 31, wid = tid >> 5;
    unsigned long long acc2[8][4];
#pragma unroll
    for (int r = 0; r < 8; r++)
#pragma unroll
        for (int c = 0; c < 4; c++) acc2[r][c] = 0ull;

    const float* xbase = sX + (wid * 8) * DD;
#pragma unroll 2
    for (int m = 0; m < 64; m++) {
        const ulonglong2* wrow = (const ulonglong2*)(sWp + m * DD + lane * 4);
        ulonglong2 wa = wrow[0];  // cols 4l, 4l+1
        ulonglong2 wb = wrow[1];  // cols 4l+2, 4l+3
#pragma unroll
        for (int r = 0; r < 8; r++) {
            unsigned long long xp =
                *(const unsigned long long*)(xbase + r * DD + 2 * m);
            FFMA2(acc2[r][0], xp, wa.x);
            FFMA2(acc2[r][1], xp, wa.y);
            FFMA2(acc2[r][2], xp, wb.x);
            FFMA2(acc2[r][3], xp, wb.y);
        }
    }

#pragma unroll
    for (int r = 0; r < 8; r++) {
        int row = row0 + wid * 8 + r;
        if (row < M) {
            float dv = g_dinv[row];
            float4 a;
            a.x = pairsum(acc2[r][0]) * dv;
            a.y = pairsum(acc2[r][1]) * dv;
            a.z = pairsum(acc2[r][2]) * dv;
            a.w = pairsum(acc2[r][3]) * dv;  // h' = dinv * h
            ((float4*)(g_h + (size_t)row * DD))[lane] = a;
        }
    }
}

// ---------------- gather-side aggregation (CSR, no float atomics) ----------------
// Warp per node: acc = h'[i] (self-loop) + sum over in-edges h'[src].
// Region: [g_off[i], g_off[i] + g_deg[i]-1). 8-way unroll -> MLP=8.
// mode 0: store agg' (layer 1). mode 1: fused readout (layer 2):
// out[i] = sigmoid((dinv*acc + b2)@Wl + bl), entirely in registers.
__global__ void gather_agg_kernel(int mode,
                                  const float* __restrict__ b2,
                                  const float* __restrict__ Wl,
                                  const float* __restrict__ bl,
                                  float* __restrict__ out, int M) {
    int i = (int)((blockIdx.x * (unsigned)blockDim.x + threadIdx.x) >> 5);
    if (i >= M) return;
    int lane = threadIdx.x & 31;

    float4 acc = ((const float4*)(g_h + (size_t)i * DD))[lane];  // self-loop
    int beg = g_off[i];
    int end = beg + g_deg[i] - 1;

    int e = beg;
    for (; e + 7 < end; e += 8) {
        int s0 = g_srclist[e];
        int s1 = g_srclist[e + 1];
        int s2 = g_srclist[e + 2];
        int s3 = g_srclist[e + 3];
        int s4 = g_srclist[e + 4];
        int s5 = g_srclist[e + 5];
        int s6 = g_srclist[e + 6];
        int s7 = g_srclist[e + 7];
        float4 v0 = ((const float4*)(g_h + (size_t)s0 * DD))[lane];
        float4 v1 = ((const float4*)(g_h + (size_t)s1 * DD))[lane];
        float4 v2 = ((const float4*)(g_h + (size_t)s2 * DD))[lane];
        float4 v3 = ((const float4*)(g_h + (size_t)s3 * DD))[lane];
        float4 v4 = ((const float4*)(g_h + (size_t)s4 * DD))[lane];
        float4 v5 = ((const float4*)(g_h + (size_t)s5 * DD))[lane];
        float4 v6 = ((const float4*)(g_h + (size_t)s6 * DD))[lane];
        float4 v7 = ((const float4*)(g_h + (size_t)s7 * DD))[lane];
        acc.x += ((v0.x + v1.x) + (v2.x + v3.x)) + ((v4.x + v5.x) + (v6.x + v7.x));
        acc.y += ((v0.y + v1.y) + (v2.y + v3.y)) + ((v4.y + v5.y) + (v6.y + v7.y));
        acc.z += ((v0.z + v1.z) + (v2.z + v3.z)) + ((v4.z + v5.z) + (v6.z + v7.z));
        acc.w += ((v0.w + v1.w) + (v2.w + v3.w)) + ((v4.w + v5.w) + (v6.w + v7.w));
    }
    for (; e + 3 < end; e += 4) {
        int s0 = g_srclist[e];
        int s1 = g_srclist[e + 1];
        int s2 = g_srclist[e + 2];
        int s3 = g_srclist[e + 3];
        float4 v0 = ((const float4*)(g_h + (size_t)s0 * DD))[lane];
        float4 v1 = ((const float4*)(g_h + (size_t)s1 * DD))[lane];
        float4 v2 = ((const float4*)(g_h + (size_t)s2 * DD))[lane];
        float4 v3 = ((const float4*)(g_h + (size_t)s3 * DD))[lane];
        acc.x += (v0.x + v1.x) + (v2.x + v3.x);
        acc.y += (v0.y + v1.y) + (v2.y + v3.y);
        acc.z += (v0.z + v1.z) + (v2.z + v3.z);
        acc.w += (v0.w + v1.w) + (v2.w + v3.w);
    }
    for (; e < end; e++) {
        int s = g_srclist[e];
        float4 v = ((const float4*)(g_h + (size_t)s * DD))[lane];
        acc.x += v.x; acc.y += v.y; acc.z += v.z; acc.w += v.w;
    }

    if (mode == 0) {
        ((float4*)(g_agg + (size_t)i * DD))[lane] = acc;
    } else {
        float dv = g_dinv[i];
        float4 b = ((const float4*)b2)[lane];
        float4 w = ((const float4*)Wl)[lane];
        float p = fmaf(dv, acc.x, b.x) * w.x + fmaf(dv, acc.y, b.y) * w.y +
                  fmaf(dv, acc.z, b.z) * w.z + fmaf(dv, acc.w, b.w) * w.w;
#pragma unroll
        for (int o = 16; o; o >>= 1) p += __shfl_down_sync(0xffffffffu, p, o);
        if (lane == 0) out[i] = 1.f / (1.f + expf(-(p + bl[0])));
    }
}

// ---------------- launch ----------------

extern "C" void kernel_launch(void* const* d_in, const int* in_sizes, int n_in,
                              void* d_out, int out_size) {
    const float* x  = (const float*)d_in[0];
    const void*  ei = d_in[1];                // int32 or int64 — detected on device
    const float* W1 = (const float*)d_in[2];
    const float* b1 = (const float*)d_in[3];
    const float* W2 = (const float*)d_in[4];
    const float* b2 = (const float*)d_in[5];
    const float* Wl = (const float*)d_in[6];
    const float* bl = (const float*)d_in[7];
    float* out = (float*)d_out;

    int E = in_sizes[1] / 2;      // element count / 2 = edges (either dtype)
    int M = in_sizes[0] / DD;

    const int GEMM_SMEM = (DD * DD + 64 * DD) * (int)sizeof(float);  // 96KB
    cudaFuncSetAttribute(gemm_kernel, cudaFuncAttributeMaxDynamicSharedMemorySize, GEMM_SMEM);

    int nb_nodes  = (NN + 255) / 256;
    int nb_edges  = (E + 255) / 256;
    int nb_gemm   = (M + 63) / 64;
    int nb_rows32 = (M * 32 + 255) / 256;

    // ---- prep: dtype detect, degrees, dinv + CSR offsets (no scan), fill ----
    deg_init_kernel<<<nb_nodes, 256>>>();
    detect_kernel<<<1, 64>>>((const int*)ei);
    pack_count_kernel<<<nb_edges, 256>>>(ei, E);
    dinv_off_kernel<<<nb_nodes, 256>>>();
    fill_kernel<<<nb_edges, 256>>>(E);

    // layer 1: h' = dinv * (x @ W1) ; agg' = gather(h')
    gemm_kernel<<<nb_gemm, 256, GEMM_SMEM>>>(x, W1, nullptr, 0, 0, M);
    gather_agg_kernel<<<nb_rows32, 256>>>(0, nullptr, nullptr, nullptr, nullptr, M);

    // layer 2: h' = dinv * (relu(dinv*agg' + b1) @ W2) ; fused gather + readout
    gemm_kernel<<<nb_gemm, 256, GEMM_SMEM>>>(nullptr, W2, b1, 1, 1, M);
    gather_agg_kernel<<<nb_rows32, 256>>>(1, b2, Wl, bl, out, M);
}